// round 1
// baseline (speedup 1.0000x reference)
#include <cuda_runtime.h>

// Problem constants
constexpr int kB = 4, kS = 2048, kD = 1024, kH = 16, kDK = 64;

// Scratch (device globals; allocation-free per harness rules)
__device__ float g_qt[(size_t)kB * kH * kDK * kS];  // Q transposed: [b,h,dk,s]
__device__ float g_kt[(size_t)kB * kH * kDK * kS];  // K transposed: [b,h,dk,s]
__device__ float g_v [(size_t)kB * kH * kS * kDK];  // V natural:    [b,h,s,dv]
__device__ float g_ao[(size_t)kB * kS * kH * kDK];  // attn out:     [b,s,h*dv]

// ---------------------------------------------------------------------------
// Kernel 1: QKV projection GEMM. C[64x64] tile per block.
// grid.x = (B*S)/64 = 128 (M tiles), grid.y = 48 (mat in {q,k,v} x 16 heads)
// ---------------------------------------------------------------------------
__global__ __launch_bounds__(256) void qkv_kernel(
    const float* __restrict__ x, const float* __restrict__ Wq,
    const float* __restrict__ Wk, const float* __restrict__ Wv) {
  __shared__ float As[32][68];  // x tile, transposed [d][m], padded
  __shared__ float Bs[32][68];  // W tile [d][k]
  const int m0 = blockIdx.x * 64;
  const int mat = blockIdx.y >> 4;
  const int h = blockIdx.y & 15;
  const float* W = (mat == 0 ? Wq : (mat == 1 ? Wk : Wv)) + (size_t)h * kD * kDK;
  const int tid = threadIdx.x;
  const int ty = tid >> 4, tx = tid & 15;

  float acc[4][4];
#pragma unroll
  for (int i = 0; i < 4; ++i)
#pragma unroll
    for (int j = 0; j < 4; ++j) acc[i][j] = 0.f;

  for (int d0 = 0; d0 < kD; d0 += 32) {
#pragma unroll
    for (int it = 0; it < 8; ++it) {
      int lin = tid + it * 256;
      int r = lin >> 5, dd = lin & 31;
      As[dd][r] = x[(size_t)(m0 + r) * kD + d0 + dd];
    }
#pragma unroll
    for (int it = 0; it < 8; ++it) {
      int lin = tid + it * 256;
      int d = lin >> 6, k = lin & 63;
      Bs[d][k] = W[(size_t)(d0 + d) * kDK + k];
    }
    __syncthreads();
#pragma unroll 8
    for (int kk = 0; kk < 32; ++kk) {
      float4 a4 = *(const float4*)&As[kk][ty * 4];
      float4 b4 = *(const float4*)&Bs[kk][tx * 4];
      float a[4] = {a4.x, a4.y, a4.z, a4.w};
      float b[4] = {b4.x, b4.y, b4.z, b4.w};
#pragma unroll
      for (int i = 0; i < 4; ++i)
#pragma unroll
        for (int j = 0; j < 4; ++j) acc[i][j] += a[i] * b[j];
    }
    __syncthreads();
  }

  const int b = m0 / kS;
  const int s0 = m0 % kS;
  if (mat < 2) {
    // store transposed: [b,h,dk,s]; float4 along s keeps stores fully coalesced
    float* outp = (mat == 0) ? g_qt : g_kt;
    const size_t base = (size_t)(b * kH + h) * kDK;
#pragma unroll
    for (int j = 0; j < 4; ++j) {
      size_t col = (base + tx * 4 + j) * kS + s0 + ty * 4;
      *(float4*)&outp[col] = make_float4(acc[0][j], acc[1][j], acc[2][j], acc[3][j]);
    }
  } else {
    const size_t base = (size_t)(b * kH + h) * kS;
#pragma unroll
    for (int i = 0; i < 4; ++i) {
      *(float4*)&g_v[(base + s0 + ty * 4 + i) * kDK + tx * 4] =
          make_float4(acc[i][0], acc[i][1], acc[i][2], acc[i][3]);
    }
  }
}

// ---------------------------------------------------------------------------
// Kernel 2: fused flash attention, fp32, online softmax.
// block = (q-tile of 64, head, batch); 256 threads (16x16), 4x4 per thread.
// Smem: Qs[64][64] + Ks[64][64] (reused as P) + Vs[64][64] = 48KB exactly.
// ---------------------------------------------------------------------------
__global__ __launch_bounds__(256) void attn_kernel() {
  __shared__ float Qs[64 * 64];  // [d][qrow]
  __shared__ float Ks[64 * 64];  // [d][kcol]; reused as Ps[qrow][kcol]
  __shared__ float Vs[64 * 64];  // [kcol][vd]
  const int qt = blockIdx.x, h = blockIdx.y, b = blockIdx.z;
  const int tid = threadIdx.x;
  const int ty = tid >> 4, tx = tid & 15;
  const size_t tbase = (size_t)(b * kH + h) * kDK * kS;  // for g_qt / g_kt
  const size_t vbase = (size_t)(b * kH + h) * kS * kDK;  // for g_v

  // load Q tile (scale 1/sqrt(64) folded in). Layout [d][row], conflict-free.
#pragma unroll
  for (int it = 0; it < 16; ++it) {
    int lin = tid + it * 256;
    int dd = lin >> 6, r = lin & 63;
    Qs[dd * 64 + r] = g_qt[tbase + (size_t)dd * kS + qt * 64 + r] * 0.125f;
  }

  float m_[4], l_[4], o_[4][4];
#pragma unroll
  for (int i = 0; i < 4; ++i) {
    m_[i] = -3.0e38f;
    l_[i] = 0.f;
#pragma unroll
    for (int j = 0; j < 4; ++j) o_[i][j] = 0.f;
  }

  for (int kt = 0; kt < kS / 64; ++kt) {
#pragma unroll
    for (int it = 0; it < 16; ++it) {
      int lin = tid + it * 256;
      int dd = lin >> 6, c = lin & 63;
      Ks[dd * 64 + c] = g_kt[tbase + (size_t)dd * kS + kt * 64 + c];
    }
#pragma unroll
    for (int it = 0; it < 16; ++it) {
      int lin = tid + it * 256;
      int c = lin >> 6, dd = lin & 63;
      Vs[c * 64 + dd] = g_v[vbase + (size_t)(kt * 64 + c) * kDK + dd];
    }
    __syncthreads();  // tiles ready (also orders Qs on first iteration)

    // S = Q^T K : 4x4 per thread
    float s_[4][4];
#pragma unroll
    for (int i = 0; i < 4; ++i)
#pragma unroll
      for (int j = 0; j < 4; ++j) s_[i][j] = 0.f;
#pragma unroll 8
    for (int kk = 0; kk < 64; ++kk) {
      float4 q4 = *(const float4*)&Qs[kk * 64 + ty * 4];
      float4 k4 = *(const float4*)&Ks[kk * 64 + tx * 4];
      float a[4] = {q4.x, q4.y, q4.z, q4.w};
      float c4[4] = {k4.x, k4.y, k4.z, k4.w};
#pragma unroll
      for (int i = 0; i < 4; ++i)
#pragma unroll
        for (int j = 0; j < 4; ++j) s_[i][j] += a[i] * c4[j];
    }
    __syncthreads();  // everyone done reading Ks -> reuse as Ps

    float* Ps = Ks;
#pragma unroll
    for (int i = 0; i < 4; ++i) {
      float mx = fmaxf(fmaxf(s_[i][0], s_[i][1]), fmaxf(s_[i][2], s_[i][3]));
      mx = fmaxf(mx, __shfl_xor_sync(0xffffffffu, mx, 1));
      mx = fmaxf(mx, __shfl_xor_sync(0xffffffffu, mx, 2));
      mx = fmaxf(mx, __shfl_xor_sync(0xffffffffu, mx, 4));
      mx = fmaxf(mx, __shfl_xor_sync(0xffffffffu, mx, 8));
      float mnew = fmaxf(m_[i], mx);
      float corr = __expf(m_[i] - mnew);
      m_[i] = mnew;
      float rs = 0.f;
#pragma unroll
      for (int j = 0; j < 4; ++j) {
        s_[i][j] = __expf(s_[i][j] - mnew);
        rs += s_[i][j];
      }
      rs += __shfl_xor_sync(0xffffffffu, rs, 1);
      rs += __shfl_xor_sync(0xffffffffu, rs, 2);
      rs += __shfl_xor_sync(0xffffffffu, rs, 4);
      rs += __shfl_xor_sync(0xffffffffu, rs, 8);
      l_[i] = l_[i] * corr + rs;
#pragma unroll
      for (int j = 0; j < 4; ++j) o_[i][j] *= corr;
      *(float4*)&Ps[(ty * 4 + i) * 64 + tx * 4] =
          make_float4(s_[i][0], s_[i][1], s_[i][2], s_[i][3]);
    }
    __syncthreads();  // P visible to all

    // O += P V
#pragma unroll 8
    for (int c = 0; c < 64; ++c) {
      float4 v4 = *(const float4*)&Vs[c * 64 + tx * 4];
      float vb[4] = {v4.x, v4.y, v4.z, v4.w};
      float p0 = Ps[(ty * 4 + 0) * 64 + c];
      float p1 = Ps[(ty * 4 + 1) * 64 + c];
      float p2 = Ps[(ty * 4 + 2) * 64 + c];
      float p3 = Ps[(ty * 4 + 3) * 64 + c];
#pragma unroll
      for (int j = 0; j < 4; ++j) {
        o_[0][j] += p0 * vb[j];
        o_[1][j] += p1 * vb[j];
        o_[2][j] += p2 * vb[j];
        o_[3][j] += p3 * vb[j];
      }
    }
    __syncthreads();  // done with Ps/Vs before next tile load
  }

#pragma unroll
  for (int i = 0; i < 4; ++i) {
    float inv = 1.f / l_[i];
    int s = qt * 64 + ty * 4 + i;
    *(float4*)&g_ao[((size_t)b * kS + s) * (kH * kDK) + h * kDK + tx * 4] =
        make_float4(o_[i][0] * inv, o_[i][1] * inv, o_[i][2] * inv, o_[i][3] * inv);
  }
}

// ---------------------------------------------------------------------------
// Kernel 3: output projection. [8192,1024] x [1024,1024] -> d_out
// ---------------------------------------------------------------------------
__global__ __launch_bounds__(256) void proj_kernel(const float* __restrict__ Wo,
                                                   float* __restrict__ out) {
  __shared__ float As[32][68];
  __shared__ float Bs[32][68];
  const int m0 = blockIdx.x * 64;
  const int n0 = blockIdx.y * 64;
  const int tid = threadIdx.x;
  const int ty = tid >> 4, tx = tid & 15;

  float acc[4][4];
#pragma unroll
  for (int i = 0; i < 4; ++i)
#pragma unroll
    for (int j = 0; j < 4; ++j) acc[i][j] = 0.f;

  for (int d0 = 0; d0 < kD; d0 += 32) {
#pragma unroll
    for (int it = 0; it < 8; ++it) {
      int lin = tid + it * 256;
      int r = lin >> 5, dd = lin & 31;
      As[dd][r] = g_ao[(size_t)(m0 + r) * kD + d0 + dd];
    }
#pragma unroll
    for (int it = 0; it < 8; ++it) {
      int lin = tid + it * 256;
      int d = lin >> 6, k = lin & 63;
      Bs[d][k] = Wo[(size_t)(d0 + d) * kD + n0 + k];
    }
    __syncthreads();
#pragma unroll 8
    for (int kk = 0; kk < 32; ++kk) {
      float4 a4 = *(const float4*)&As[kk][ty * 4];
      float4 b4 = *(const float4*)&Bs[kk][tx * 4];
      float a[4] = {a4.x, a4.y, a4.z, a4.w};
      float b[4] = {b4.x, b4.y, b4.z, b4.w};
#pragma unroll
      for (int i = 0; i < 4; ++i)
#pragma unroll
        for (int j = 0; j < 4; ++j) acc[i][j] += a[i] * b[j];
    }
    __syncthreads();
  }
#pragma unroll
  for (int i = 0; i < 4; ++i) {
    *(float4*)&out[(size_t)(m0 + ty * 4 + i) * kD + n0 + tx * 4] =
        make_float4(acc[i][0], acc[i][1], acc[i][2], acc[i][3]);
  }
}

extern "C" void kernel_launch(void* const* d_in, const int* in_sizes, int n_in,
                              void* d_out, int out_size) {
  (void)in_sizes; (void)n_in; (void)out_size;
  const float* x  = (const float*)d_in[0];
  const float* Wq = (const float*)d_in[1];
  const float* Wk = (const float*)d_in[2];
  const float* Wv = (const float*)d_in[3];
  const float* Wo = (const float*)d_in[4];
  float* out = (float*)d_out;

  qkv_kernel<<<dim3(kB * kS / 64, 48), 256>>>(x, Wq, Wk, Wv);
  attn_kernel<<<dim3(kS / 64, kH, kB), 256>>>();
  proj_kernel<<<dim3(kB * kS / 64, kD / 64), 256>>>(Wo, out);
}

// round 2
// speedup vs baseline: 1.0004x; 1.0004x over previous
#include <cuda_runtime.h>

// Problem constants
constexpr int kB = 4, kS = 2048, kD = 1024, kH = 16, kDK = 64;

// Scratch (device globals; allocation-free per harness rules)
__device__ float g_qt[(size_t)kB * kH * kDK * kS];  // Q transposed: [b,h,dk,s]
__device__ float g_kt[(size_t)kB * kH * kDK * kS];  // K transposed: [b,h,dk,s]
__device__ float g_v [(size_t)kB * kH * kS * kDK];  // V natural:    [b,h,s,dv]
__device__ float g_ao[(size_t)kB * kS * kH * kDK];  // attn out:     [b,s,h*dv]

// ---------------------------------------------------------------------------
// Kernel 1: QKV projection GEMM. C[64x64] tile per block.
// grid.x = (B*S)/64 = 128 (M tiles), grid.y = 48 (mat in {q,k,v} x 16 heads)
// ---------------------------------------------------------------------------
__global__ __launch_bounds__(256) void qkv_kernel(
    const float* __restrict__ x, const float* __restrict__ Wq,
    const float* __restrict__ Wk, const float* __restrict__ Wv) {
  __shared__ float As[32][68];  // x tile, transposed [d][m], padded
  __shared__ float Bs[32][68];  // W tile [d][k]
  const int m0 = blockIdx.x * 64;
  const int mat = blockIdx.y >> 4;
  const int h = blockIdx.y & 15;
  const float* W = (mat == 0 ? Wq : (mat == 1 ? Wk : Wv)) + (size_t)h * kD * kDK;
  const int tid = threadIdx.x;
  const int ty = tid >> 4, tx = tid & 15;

  float acc[4][4];
#pragma unroll
  for (int i = 0; i < 4; ++i)
#pragma unroll
    for (int j = 0; j < 4; ++j) acc[i][j] = 0.f;

  for (int d0 = 0; d0 < kD; d0 += 32) {
#pragma unroll
    for (int it = 0; it < 8; ++it) {
      int lin = tid + it * 256;
      int r = lin >> 5, dd = lin & 31;
      As[dd][r] = x[(size_t)(m0 + r) * kD + d0 + dd];
    }
#pragma unroll
    for (int it = 0; it < 8; ++it) {
      int lin = tid + it * 256;
      int d = lin >> 6, k = lin & 63;
      Bs[d][k] = W[(size_t)(d0 + d) * kDK + k];
    }
    __syncthreads();
#pragma unroll 8
    for (int kk = 0; kk < 32; ++kk) {
      float4 a4 = *(const float4*)&As[kk][ty * 4];
      float4 b4 = *(const float4*)&Bs[kk][tx * 4];
      float a[4] = {a4.x, a4.y, a4.z, a4.w};
      float b[4] = {b4.x, b4.y, b4.z, b4.w};
#pragma unroll
      for (int i = 0; i < 4; ++i)
#pragma unroll
        for (int j = 0; j < 4; ++j) acc[i][j] += a[i] * b[j];
    }
    __syncthreads();
  }

  const int b = m0 / kS;
  const int s0 = m0 % kS;
  if (mat < 2) {
    // store transposed: [b,h,dk,s]; float4 along s keeps stores fully coalesced
    float* outp = (mat == 0) ? g_qt : g_kt;
    const size_t base = (size_t)(b * kH + h) * kDK;
#pragma unroll
    for (int j = 0; j < 4; ++j) {
      size_t col = (base + tx * 4 + j) * kS + s0 + ty * 4;
      *(float4*)&outp[col] = make_float4(acc[0][j], acc[1][j], acc[2][j], acc[3][j]);
    }
  } else {
    const size_t base = (size_t)(b * kH + h) * kS;
#pragma unroll
    for (int i = 0; i < 4; ++i) {
      *(float4*)&g_v[(base + s0 + ty * 4 + i) * kDK + tx * 4] =
          make_float4(acc[i][0], acc[i][1], acc[i][2], acc[i][3]);
    }
  }
}

// ---------------------------------------------------------------------------
// Kernel 2: fused flash attention, fp32, online softmax.
// block = (q-tile of 64, head, batch); 256 threads (16x16), 4x4 per thread.
// Smem: Qs[64][64] + Ks[64][64] (reused as P) + Vs[64][64] = 48KB exactly.
// ---------------------------------------------------------------------------
__global__ __launch_bounds__(256) void attn_kernel() {
  __shared__ float Qs[64 * 64];  // [d][qrow]
  __shared__ float Ks[64 * 64];  // [d][kcol]; reused as Ps[qrow][kcol]
  __shared__ float Vs[64 * 64];  // [kcol][vd]
  const int qt = blockIdx.x, h = blockIdx.y, b = blockIdx.z;
  const int tid = threadIdx.x;
  const int ty = tid >> 4, tx = tid & 15;
  const size_t tbase = (size_t)(b * kH + h) * kDK * kS;  // for g_qt / g_kt
  const size_t vbase = (size_t)(b * kH + h) * kS * kDK;  // for g_v

  // load Q tile (scale 1/sqrt(64) folded in). Layout [d][row], conflict-free.
#pragma unroll
  for (int it = 0; it < 16; ++it) {
    int lin = tid + it * 256;
    int dd = lin >> 6, r = lin & 63;
    Qs[dd * 64 + r] = g_qt[tbase + (size_t)dd * kS + qt * 64 + r] * 0.125f;
  }

  float m_[4], l_[4], o_[4][4];
#pragma unroll
  for (int i = 0; i < 4; ++i) {
    m_[i] = -3.0e38f;
    l_[i] = 0.f;
#pragma unroll
    for (int j = 0; j < 4; ++j) o_[i][j] = 0.f;
  }

  for (int kt = 0; kt < kS / 64; ++kt) {
#pragma unroll
    for (int it = 0; it < 16; ++it) {
      int lin = tid + it * 256;
      int dd = lin >> 6, c = lin & 63;
      Ks[dd * 64 + c] = g_kt[tbase + (size_t)dd * kS + kt * 64 + c];
    }
#pragma unroll
    for (int it = 0; it < 16; ++it) {
      int lin = tid + it * 256;
      int c = lin >> 6, dd = lin & 63;
      Vs[c * 64 + dd] = g_v[vbase + (size_t)(kt * 64 + c) * kDK + dd];
    }
    __syncthreads();  // tiles ready (also orders Qs on first iteration)

    // S = Q^T K : 4x4 per thread
    float s_[4][4];
#pragma unroll
    for (int i = 0; i < 4; ++i)
#pragma unroll
      for (int j = 0; j < 4; ++j) s_[i][j] = 0.f;
#pragma unroll 8
    for (int kk = 0; kk < 64; ++kk) {
      float4 q4 = *(const float4*)&Qs[kk * 64 + ty * 4];
      float4 k4 = *(const float4*)&Ks[kk * 64 + tx * 4];
      float a[4] = {q4.x, q4.y, q4.z, q4.w};
      float c4[4] = {k4.x, k4.y, k4.z, k4.w};
#pragma unroll
      for (int i = 0; i < 4; ++i)
#pragma unroll
        for (int j = 0; j < 4; ++j) s_[i][j] += a[i] * c4[j];
    }
    __syncthreads();  // everyone done reading Ks -> reuse as Ps

    float* Ps = Ks;
#pragma unroll
    for (int i = 0; i < 4; ++i) {
      float mx = fmaxf(fmaxf(s_[i][0], s_[i][1]), fmaxf(s_[i][2], s_[i][3]));
      mx = fmaxf(mx, __shfl_xor_sync(0xffffffffu, mx, 1));
      mx = fmaxf(mx, __shfl_xor_sync(0xffffffffu, mx, 2));
      mx = fmaxf(mx, __shfl_xor_sync(0xffffffffu, mx, 4));
      mx = fmaxf(mx, __shfl_xor_sync(0xffffffffu, mx, 8));
      float mnew = fmaxf(m_[i], mx);
      float corr = __expf(m_[i] - mnew);
      m_[i] = mnew;
      float rs = 0.f;
#pragma unroll
      for (int j = 0; j < 4; ++j) {
        s_[i][j] = __expf(s_[i][j] - mnew);
        rs += s_[i][j];
      }
      rs += __shfl_xor_sync(0xffffffffu, rs, 1);
      rs += __shfl_xor_sync(0xffffffffu, rs, 2);
      rs += __shfl_xor_sync(0xffffffffu, rs, 4);
      rs += __shfl_xor_sync(0xffffffffu, rs, 8);
      l_[i] = l_[i] * corr + rs;
#pragma unroll
      for (int j = 0; j < 4; ++j) o_[i][j] *= corr;
      *(float4*)&Ps[(ty * 4 + i) * 64 + tx * 4] =
          make_float4(s_[i][0], s_[i][1], s_[i][2], s_[i][3]);
    }
    __syncthreads();  // P visible to all

    // O += P V
#pragma unroll 8
    for (int c = 0; c < 64; ++c) {
      float4 v4 = *(const float4*)&Vs[c * 64 + tx * 4];
      float vb[4] = {v4.x, v4.y, v4.z, v4.w};
      float p0 = Ps[(ty * 4 + 0) * 64 + c];
      float p1 = Ps[(ty * 4 + 1) * 64 + c];
      float p2 = Ps[(ty * 4 + 2) * 64 + c];
      float p3 = Ps[(ty * 4 + 3) * 64 + c];
#pragma unroll
      for (int j = 0; j < 4; ++j) {
        o_[0][j] += p0 * vb[j];
        o_[1][j] += p1 * vb[j];
        o_[2][j] += p2 * vb[j];
        o_[3][j] += p3 * vb[j];
      }
    }
    __syncthreads();  // done with Ps/Vs before next tile load
  }

#pragma unroll
  for (int i = 0; i < 4; ++i) {
    float inv = 1.f / l_[i];
    int s = qt * 64 + ty * 4 + i;
    *(float4*)&g_ao[((size_t)b * kS + s) * (kH * kDK) + h * kDK + tx * 4] =
        make_float4(o_[i][0] * inv, o_[i][1] * inv, o_[i][2] * inv, o_[i][3] * inv);
  }
}

// ---------------------------------------------------------------------------
// Kernel 3: output projection. [8192,1024] x [1024,1024] -> d_out
// ---------------------------------------------------------------------------
__global__ __launch_bounds__(256) void proj_kernel(const float* __restrict__ Wo,
                                                   float* __restrict__ out) {
  __shared__ float As[32][68];
  __shared__ float Bs[32][68];
  const int m0 = blockIdx.x * 64;
  const int n0 = blockIdx.y * 64;
  const int tid = threadIdx.x;
  const int ty = tid >> 4, tx = tid & 15;

  float acc[4][4];
#pragma unroll
  for (int i = 0; i < 4; ++i)
#pragma unroll
    for (int j = 0; j < 4; ++j) acc[i][j] = 0.f;

  for (int d0 = 0; d0 < kD; d0 += 32) {
#pragma unroll
    for (int it = 0; it < 8; ++it) {
      int lin = tid + it * 256;
      int r = lin >> 5, dd = lin & 31;
      As[dd][r] = g_ao[(size_t)(m0 + r) * kD + d0 + dd];
    }
#pragma unroll
    for (int it = 0; it < 8; ++it) {
      int lin = tid + it * 256;
      int d = lin >> 6, k = lin & 63;
      Bs[d][k] = Wo[(size_t)(d0 + d) * kD + n0 + k];
    }
    __syncthreads();
#pragma unroll 8
    for (int kk = 0; kk < 32; ++kk) {
      float4 a4 = *(const float4*)&As[kk][ty * 4];
      float4 b4 = *(const float4*)&Bs[kk][tx * 4];
      float a[4] = {a4.x, a4.y, a4.z, a4.w};
      float b[4] = {b4.x, b4.y, b4.z, b4.w};
#pragma unroll
      for (int i = 0; i < 4; ++i)
#pragma unroll
        for (int j = 0; j < 4; ++j) acc[i][j] += a[i] * b[j];
    }
    __syncthreads();
  }
#pragma unroll
  for (int i = 0; i < 4; ++i) {
    *(float4*)&out[(size_t)(m0 + ty * 4 + i) * kD + n0 + tx * 4] =
        make_float4(acc[i][0], acc[i][1], acc[i][2], acc[i][3]);
  }
}

extern "C" void kernel_launch(void* const* d_in, const int* in_sizes, int n_in,
                              void* d_out, int out_size) {
  (void)in_sizes; (void)n_in; (void)out_size;
  const float* x  = (const float*)d_in[0];
  const float* Wq = (const float*)d_in[1];
  const float* Wk = (const float*)d_in[2];
  const float* Wv = (const float*)d_in[3];
  const float* Wo = (const float*)d_in[4];
  float* out = (float*)d_out;

  qkv_kernel<<<dim3(kB * kS / 64, 48), 256>>>(x, Wq, Wk, Wv);
  attn_kernel<<<dim3(kS / 64, kH, kB), 256>>>();
  proj_kernel<<<dim3(kB * kS / 64, kD / 64), 256>>>(Wo, out);
}

// round 3
// speedup vs baseline: 1.1721x; 1.1716x over previous
#include <cuda_runtime.h>

constexpr int kB = 4, kS = 2048, kD = 1024, kH = 16, kDK = 64;

using u64 = unsigned long long;

__device__ __forceinline__ void fma2(u64& d, u64 a, u64 b) {
  asm("fma.rn.f32x2 %0, %1, %2, %0;" : "+l"(d) : "l"(a), "l"(b));
}
__device__ __forceinline__ void mul2(u64& d, u64 a) {
  asm("mul.rn.f32x2 %0, %0, %1;" : "+l"(d) : "l"(a));
}
__device__ __forceinline__ u64 pack2(float x, float y) {
  u64 r; asm("mov.b64 %0, {%1,%2};" : "=l"(r) : "f"(x), "f"(y)); return r;
}
__device__ __forceinline__ float2 unpack2(u64 p) {
  float x, y; asm("mov.b64 {%0,%1}, %2;" : "=f"(x), "=f"(y) : "l"(p));
  return make_float2(x, y);
}

// Scratch (device globals; allocation-free per harness rules)
__device__ float g_q [(size_t)kB * kH * kS * kDK];  // Q natural [b,h,s,dk]
__device__ float g_kt[(size_t)kB * kH * kDK * kS];  // K^T      [b,h,dk,s]
__device__ float g_v [(size_t)kB * kH * kS * kDK];  // V natural [b,h,s,dv]
__device__ float g_ao[(size_t)kB * kS * kH * kDK];  // attn out  [b,s,h*dv]

// ---------------------------------------------------------------------------
// Kernel 1: QKV projections. Tile 128(M)x64(N), 128 threads, 8x8/thread, f32x2.
// grid = (64 m-tiles, 48 = {q,k,v} x 16 heads)
// ---------------------------------------------------------------------------
__global__ __launch_bounds__(128) void qkv_kernel(
    const float* __restrict__ x, const float* __restrict__ Wq,
    const float* __restrict__ Wk, const float* __restrict__ Wv) {
  __shared__ float As[128][36];  // x tile, natural [m][kk]
  __shared__ float Bs[32][72];   // W tile [kk][n]
  const int m0 = blockIdx.x * 128;
  const int mat = blockIdx.y >> 4;
  const int h = blockIdx.y & 15;
  const float* W = (mat == 0 ? Wq : (mat == 1 ? Wk : Wv)) + (size_t)h * kD * kDK;
  const int tid = threadIdx.x;
  const int ty = tid >> 3, tx = tid & 7;

  u64 acc[8][4];
#pragma unroll
  for (int i = 0; i < 8; ++i)
#pragma unroll
    for (int j = 0; j < 4; ++j) acc[i][j] = 0ull;

  for (int d0 = 0; d0 < kD; d0 += 32) {
#pragma unroll
    for (int it = 0; it < 8; ++it) {
      int lin = tid + it * 128;
      int r = lin >> 3, dq = lin & 7;
      *(float4*)&As[r][dq * 4] =
          *(const float4*)&x[(size_t)(m0 + r) * kD + d0 + dq * 4];
    }
#pragma unroll
    for (int it = 0; it < 4; ++it) {
      int lin = tid + it * 128;
      int kr = lin >> 4, n4 = lin & 15;
      *(float4*)&Bs[kr][n4 * 4] =
          *(const float4*)&W[(size_t)(d0 + kr) * kDK + n4 * 4];
    }
    __syncthreads();
#pragma unroll 8
    for (int kk = 0; kk < 32; ++kk) {
      ulonglong2 bA = *(const ulonglong2*)&Bs[kk][tx * 8];
      ulonglong2 bB = *(const ulonglong2*)&Bs[kk][tx * 8 + 4];
#pragma unroll
      for (int i = 0; i < 8; ++i) {
        float av = As[ty * 8 + i][kk];
        u64 aa = pack2(av, av);
        fma2(acc[i][0], aa, bA.x);
        fma2(acc[i][1], aa, bA.y);
        fma2(acc[i][2], aa, bB.x);
        fma2(acc[i][3], aa, bB.y);
      }
    }
    __syncthreads();
  }

  const int bh = (m0 >> 11) * kH + h;
  const int s0 = m0 & (kS - 1);
  if (mat == 1) {
    // K^T store: [b,h,dk,s]
#pragma unroll
    for (int j2 = 0; j2 < 4; ++j2) {
      float2 u0 = unpack2(acc[0][j2]), u1 = unpack2(acc[1][j2]);
      float2 u2 = unpack2(acc[2][j2]), u3 = unpack2(acc[3][j2]);
      float2 u4 = unpack2(acc[4][j2]), u5 = unpack2(acc[5][j2]);
      float2 u6 = unpack2(acc[6][j2]), u7 = unpack2(acc[7][j2]);
      int c0 = tx * 8 + 2 * j2;
      float* d0p = &g_kt[((size_t)bh * kDK + c0) * kS + s0 + ty * 8];
      *(float4*)d0p = make_float4(u0.x, u1.x, u2.x, u3.x);
      *(float4*)(d0p + 4) = make_float4(u4.x, u5.x, u6.x, u7.x);
      float* d1p = &g_kt[((size_t)bh * kDK + c0 + 1) * kS + s0 + ty * 8];
      *(float4*)d1p = make_float4(u0.y, u1.y, u2.y, u3.y);
      *(float4*)(d1p + 4) = make_float4(u4.y, u5.y, u6.y, u7.y);
    }
  } else {
    float* outp = (mat == 0) ? g_q : g_v;
#pragma unroll
    for (int i = 0; i < 8; ++i) {
      float2 u0 = unpack2(acc[i][0]), u1 = unpack2(acc[i][1]);
      float2 u2 = unpack2(acc[i][2]), u3 = unpack2(acc[i][3]);
      float* dp = &outp[((size_t)bh * kS + s0 + ty * 8 + i) * kDK + tx * 8];
      *(float4*)dp = make_float4(u0.x, u0.y, u1.x, u1.y);
      *(float4*)(dp + 4) = make_float4(u2.x, u2.y, u3.x, u3.y);
    }
  }
}

// ---------------------------------------------------------------------------
// Kernel 2: fused flash attention. 128q-tile, 64k-tiles, 128 threads,
// 8q x 8dv per thread, f32x2 MACs, register-resident P via shfl broadcast.
// Dynamic smem: Qs[128][68] + Ks[64][72] + Vs[64][72] = 71680 B.
// ---------------------------------------------------------------------------
__global__ __launch_bounds__(128, 2) void attn_kernel() {
  extern __shared__ float sm[];
  float* Qs = sm;                  // [q][dk]  stride 68
  float* Ks = sm + 128 * 68;       // [dk][c]  stride 72
  float* Vs = Ks + 64 * 72;        // [c][dv]  stride 72
  const int qt = blockIdx.x, h = blockIdx.y, b = blockIdx.z;
  const int bh = b * kH + h;
  const int tid = threadIdx.x;
  const int ty = tid >> 3, tx = tid & 7;
  const int lane = tid & 31;

  const float* qsrc = g_q + ((size_t)bh * kS + qt * 128) * kDK;
#pragma unroll
  for (int it = 0; it < 16; ++it) {
    int lin = tid + it * 128;
    int r = lin >> 4, dq = lin & 15;
    float4 v = *(const float4*)&qsrc[(size_t)r * kDK + dq * 4];
    v.x *= 0.125f; v.y *= 0.125f; v.z *= 0.125f; v.w *= 0.125f;
    *(float4*)&Qs[r * 68 + dq * 4] = v;
  }

  u64 o2[8][4];
  float m_[8], l_[8];
#pragma unroll
  for (int i = 0; i < 8; ++i) {
    m_[i] = -3.0e38f;
    l_[i] = 0.f;
#pragma unroll
    for (int j = 0; j < 4; ++j) o2[i][j] = 0ull;
  }

  const float* ktbase = g_kt + (size_t)bh * kDK * kS;
  const float* vbase = g_v + (size_t)bh * kS * kDK;

  for (int kt = 0; kt < kS / 64; ++kt) {
#pragma unroll
    for (int it = 0; it < 8; ++it) {
      int lin = tid + it * 128;
      int dd = lin >> 4, c4 = lin & 15;
      *(float4*)&Ks[dd * 72 + c4 * 4] =
          *(const float4*)&ktbase[(size_t)dd * kS + kt * 64 + c4 * 4];
    }
#pragma unroll
    for (int it = 0; it < 8; ++it) {
      int lin = tid + it * 128;
      int c = lin >> 4, dq = lin & 15;
      *(float4*)&Vs[c * 72 + dq * 4] =
          *(const float4*)&vbase[(size_t)(kt * 64 + c) * kDK + dq * 4];
    }
    __syncthreads();

    // S = Q K^T  (pairs along k-columns)
    u64 s2[8][4];
#pragma unroll
    for (int i = 0; i < 8; ++i)
#pragma unroll
      for (int j = 0; j < 4; ++j) s2[i][j] = 0ull;
#pragma unroll 8
    for (int kk = 0; kk < 64; ++kk) {
      ulonglong2 bA = *(const ulonglong2*)&Ks[kk * 72 + tx * 8];
      ulonglong2 bB = *(const ulonglong2*)&Ks[kk * 72 + tx * 8 + 4];
#pragma unroll
      for (int i = 0; i < 8; ++i) {
        float qv = Qs[(ty * 8 + i) * 68 + kk];
        u64 aa = pack2(qv, qv);
        fma2(s2[i][0], aa, bA.x);
        fma2(s2[i][1], aa, bA.y);
        fma2(s2[i][2], aa, bB.x);
        fma2(s2[i][3], aa, bB.y);
      }
    }

    // online softmax (rows split across the 8 tx lanes of each octet)
    float sp[8][8];
#pragma unroll
    for (int i = 0; i < 8; ++i) {
      float2 u0 = unpack2(s2[i][0]), u1 = unpack2(s2[i][1]);
      float2 u2 = unpack2(s2[i][2]), u3 = unpack2(s2[i][3]);
      float sc[8] = {u0.x, u0.y, u1.x, u1.y, u2.x, u2.y, u3.x, u3.y};
      float mx = fmaxf(fmaxf(fmaxf(sc[0], sc[1]), fmaxf(sc[2], sc[3])),
                       fmaxf(fmaxf(sc[4], sc[5]), fmaxf(sc[6], sc[7])));
      mx = fmaxf(mx, __shfl_xor_sync(0xffffffffu, mx, 1));
      mx = fmaxf(mx, __shfl_xor_sync(0xffffffffu, mx, 2));
      mx = fmaxf(mx, __shfl_xor_sync(0xffffffffu, mx, 4));
      float mnew = fmaxf(m_[i], mx);
      float corr = __expf(m_[i] - mnew);
      m_[i] = mnew;
      float sum = 0.f;
#pragma unroll
      for (int j = 0; j < 8; ++j) {
        sc[j] = __expf(sc[j] - mnew);
        sum += sc[j];
        sp[i][j] = sc[j];
      }
      sum += __shfl_xor_sync(0xffffffffu, sum, 1);
      sum += __shfl_xor_sync(0xffffffffu, sum, 2);
      sum += __shfl_xor_sync(0xffffffffu, sum, 4);
      l_[i] = l_[i] * corr + sum;
      u64 cc = pack2(corr, corr);
      mul2(o2[i][0], cc); mul2(o2[i][1], cc);
      mul2(o2[i][2], cc); mul2(o2[i][3], cc);
    }

    // O += P V  (P broadcast from registers via shfl)
    for (int ct = 0; ct < 8; ++ct) {
      int src = (lane & 24) | ct;
#pragma unroll
      for (int ci = 0; ci < 8; ++ci) {
        int c = ct * 8 + ci;
        ulonglong2 vA = *(const ulonglong2*)&Vs[c * 72 + tx * 8];
        ulonglong2 vB = *(const ulonglong2*)&Vs[c * 72 + tx * 8 + 4];
#pragma unroll
        for (int i = 0; i < 8; ++i) {
          float p = __shfl_sync(0xffffffffu, sp[i][ci], src);
          u64 pp = pack2(p, p);
          fma2(o2[i][0], pp, vA.x);
          fma2(o2[i][1], pp, vA.y);
          fma2(o2[i][2], pp, vB.x);
          fma2(o2[i][3], pp, vB.y);
        }
      }
    }
    __syncthreads();
  }

#pragma unroll
  for (int i = 0; i < 8; ++i) {
    float inv = 1.f / l_[i];
    float2 u0 = unpack2(o2[i][0]), u1 = unpack2(o2[i][1]);
    float2 u2 = unpack2(o2[i][2]), u3 = unpack2(o2[i][3]);
    float* dp = &g_ao[((size_t)b * kS + qt * 128 + ty * 8 + i) * kD + h * kDK + tx * 8];
    *(float4*)dp = make_float4(u0.x * inv, u0.y * inv, u1.x * inv, u1.y * inv);
    *(float4*)(dp + 4) = make_float4(u2.x * inv, u2.y * inv, u3.x * inv, u3.y * inv);
  }
}

// ---------------------------------------------------------------------------
// Kernel 3: output projection. [8192,1024] x [1024,1024] -> d_out.
// Tile 128x64, 128 threads, 8x8/thread, f32x2. grid = (64, 16)
// ---------------------------------------------------------------------------
__global__ __launch_bounds__(128) void proj_kernel(const float* __restrict__ Wo,
                                                   float* __restrict__ out) {
  __shared__ float As[128][36];
  __shared__ float Bs[32][72];
  const int m0 = blockIdx.x * 128;
  const int n0 = blockIdx.y * 64;
  const int tid = threadIdx.x;
  const int ty = tid >> 3, tx = tid & 7;

  u64 acc[8][4];
#pragma unroll
  for (int i = 0; i < 8; ++i)
#pragma unroll
    for (int j = 0; j < 4; ++j) acc[i][j] = 0ull;

  for (int d0 = 0; d0 < kD; d0 += 32) {
#pragma unroll
    for (int it = 0; it < 8; ++it) {
      int lin = tid + it * 128;
      int r = lin >> 3, dq = lin & 7;
      *(float4*)&As[r][dq * 4] =
          *(const float4*)&g_ao[(size_t)(m0 + r) * kD + d0 + dq * 4];
    }
#pragma unroll
    for (int it = 0; it < 4; ++it) {
      int lin = tid + it * 128;
      int kr = lin >> 4, n4 = lin & 15;
      *(float4*)&Bs[kr][n4 * 4] =
          *(const float4*)&Wo[(size_t)(d0 + kr) * kD + n0 + n4 * 4];
    }
    __syncthreads();
#pragma unroll 8
    for (int kk = 0; kk < 32; ++kk) {
      ulonglong2 bA = *(const ulonglong2*)&Bs[kk][tx * 8];
      ulonglong2 bB = *(const ulonglong2*)&Bs[kk][tx * 8 + 4];
#pragma unroll
      for (int i = 0; i < 8; ++i) {
        float av = As[ty * 8 + i][kk];
        u64 aa = pack2(av, av);
        fma2(acc[i][0], aa, bA.x);
        fma2(acc[i][1], aa, bA.y);
        fma2(acc[i][2], aa, bB.x);
        fma2(acc[i][3], aa, bB.y);
      }
    }
    __syncthreads();
  }
#pragma unroll
  for (int i = 0; i < 8; ++i) {
    float2 u0 = unpack2(acc[i][0]), u1 = unpack2(acc[i][1]);
    float2 u2 = unpack2(acc[i][2]), u3 = unpack2(acc[i][3]);
    float* dp = &out[(size_t)(m0 + ty * 8 + i) * kD + n0 + tx * 8];
    *(float4*)dp = make_float4(u0.x, u0.y, u1.x, u1.y);
    *(float4*)(dp + 4) = make_float4(u2.x, u2.y, u3.x, u3.y);
  }
}

extern "C" void kernel_launch(void* const* d_in, const int* in_sizes, int n_in,
                              void* d_out, int out_size) {
  (void)in_sizes; (void)n_in; (void)out_size;
  const float* x  = (const float*)d_in[0];
  const float* Wq = (const float*)d_in[1];
  const float* Wk = (const float*)d_in[2];
  const float* Wv = (const float*)d_in[3];
  const float* Wo = (const float*)d_in[4];
  float* out = (float*)d_out;

  static int smem_set = 0;
  if (!smem_set) {
    cudaFuncSetAttribute(attn_kernel, cudaFuncAttributeMaxDynamicSharedMemorySize,
                         71680);
    smem_set = 1;
  }

  qkv_kernel<<<dim3(kB * kS / 128, 48), 128>>>(x, Wq, Wk, Wv);
  attn_kernel<<<dim3(kS / 128, kH, kB), 128, 71680>>>();
  proj_kernel<<<dim3(kB * kS / 128, kD / 64), 128>>>(Wo, out);
}